// round 11
// baseline (speedup 1.0000x reference)
#include <cuda_runtime.h>
#include <cuda_fp16.h>
#include <cstdint>

#define BB 64
#define TSTEPS 512
#define HH 512

// ---------------- static device scratch ----------------
__device__ __align__(16) __half g_xh[TSTEPS * BB * 256];        // x fp16, [T][B][256]
__device__ __align__(16) __half g_h0[(TSTEPS + 1) * BB * HH];   // layer0 h seq, slot0 = 0
__device__ __align__(16) __half g_h1[(TSTEPS + 1) * BB * HH];   // layer1 h seq, slot0 = 0
__device__ unsigned g_c0;                                       // monotonic arrival counters
__device__ unsigned g_c1;

// ---------------- PTX helpers ----------------
__device__ __forceinline__ void cp16(uint32_t dst, const void* src) {
    asm volatile("cp.async.cg.shared.global [%0], [%1], 16;\n" :: "r"(dst), "l"(src));
}
__device__ __forceinline__ void cp_commit() { asm volatile("cp.async.commit_group;\n"); }
template<int N> __device__ __forceinline__ void cp_wait() {
    asm volatile("cp.async.wait_group %0;\n" :: "n"(N));
}
__device__ __forceinline__ void ldsm4(uint32_t& r0, uint32_t& r1, uint32_t& r2, uint32_t& r3,
                                      uint32_t a) {
    asm volatile("ldmatrix.sync.aligned.m8n8.x4.shared.b16 {%0,%1,%2,%3}, [%4];\n"
                 : "=r"(r0), "=r"(r1), "=r"(r2), "=r"(r3) : "r"(a));
}
__device__ __forceinline__ void mma16816(float* c,
                                         uint32_t a0, uint32_t a1, uint32_t a2, uint32_t a3,
                                         uint32_t b0, uint32_t b1) {
    asm volatile("mma.sync.aligned.m16n8k16.row.col.f32.f16.f16.f32 "
                 "{%0,%1,%2,%3}, {%4,%5,%6,%7}, {%8,%9}, {%0,%1,%2,%3};\n"
                 : "+f"(c[0]), "+f"(c[1]), "+f"(c[2]), "+f"(c[3])
                 : "r"(a0), "r"(a1), "r"(a2), "r"(a3), "r"(b0), "r"(b1));
}
__device__ __forceinline__ unsigned ld_acq(const unsigned* p) {
    unsigned v;
    asm volatile("ld.acquire.gpu.global.u32 %0, [%1];" : "=r"(v) : "l"(p) : "memory");
    return v;
}
__device__ __forceinline__ void red_rel(unsigned* p) {
    asm volatile("red.release.gpu.global.add.u32 [%0], 1;" :: "l"(p) : "memory");
}

// ---------------- A staging: 64 rows x UNITS 16B-units, swizzled (512 thr) ----------------
template<int UNITS>
__device__ __forceinline__ void stage(uint32_t dst, int arb, const __half* src,
                                      int sstride) {
    int tid = threadIdx.x;
#pragma unroll
    for (int i = 0; i < (64 * UNITS) / 512; i++) {
        int idx = tid + i * 512;
        int r = idx / UNITS, kc = idx % UNITS;
        cp16(dst + r * arb + ((kc ^ (r & 7)) << 4), src + r * sstride + kc * 8);
    }
}

// ---------------- GEMM: warp (kq=w>>2, m=w&3) computes 16 rows x 32 cols, K slice ----------------
template<int NP>   // NP iterations of 4 units (64 halves) each
__device__ __forceinline__ void gemm4(float* acc, uint32_t asmb, int arb,
                                      uint32_t wsmb, int rowb, int au0, int wu0) {
    int tid = threadIdx.x, lane = tid & 31, w = tid >> 5;
    int m0 = (w & 3) * 16;
    int rA = m0 + (lane & 15);
    uint32_t abase = asmb + rA * arb;
    int asw = rA & 7, akc = lane >> 4;
    int bm = lane >> 3, bsw = lane & 7;
    uint32_t bb0 = wsmb + (lane & 7) * rowb;
#pragma unroll
    for (int p = 0; p < NP; p++) {
        int au = au0 + 4 * p, wu = wu0 + 4 * p;
        uint32_t a0, a1, a2, a3, a4, a5, a6, a7;
        ldsm4(a0, a1, a2, a3, abase + (((au + akc) ^ asw) << 4));
        ldsm4(a4, a5, a6, a7, abase + (((au + 2 + akc) ^ asw) << 4));
#pragma unroll
        for (int nt = 0; nt < 4; nt++) {
            uint32_t b0, b1, b2, b3;
            ldsm4(b0, b1, b2, b3, bb0 + nt * 8 * rowb + (((wu + bm) ^ bsw) << 4));
            mma16816(acc + nt * 4, a0, a1, a2, a3, b0, b1);
            mma16816(acc + nt * 4, a4, a5, a6, a7, b2, b3);
        }
    }
}

// ---------------- init kernel: x convert + h slot0 zero + counters ----------------
__global__ void init_k(const float* __restrict__ x) {
    int i = blockIdx.x * 256 + threadIdx.x;
    int f2 = i & 127;
    int t  = (i >> 7) & 511;
    int b  = i >> 16;
    float2 v = *(const float2*)(x + ((b * 512 + t) * 256 + f2 * 2));
    *((__half2*)(g_xh + (t * 64 + b) * 256 + f2 * 2)) = __floats2half2_rn(v.x, v.y);
    if (i < 16384) {
        __half2 z = __floats2half2_rn(0.f, 0.f);
        ((__half2*)g_h0)[i] = z;
        ((__half2*)g_h1)[i] = z;
    }
    if (i == 0) { g_c0 = 0; g_c1 = 0; }
}

// ---------------- fused two-layer pipelined persistent kernel ----------------
// CTAs [0,64): layer 0.  CTAs [64,128): layer 1, lagging ~2 steps (prefetch slack).
// 512 threads = 16 warps = 4(m) x 4(k-quarter); every warp computes in every phase.
// Per step: NR gemm from prefetched P buffer (off critical path), then one exposed
// stage+gemm of the own recurrence (K=512), pointwise, release, prefetch P(t+1).
template<int GRP>
__device__ __forceinline__ void run_group(char* dsm, int lx,
        const float* __restrict__ Wih, const float* __restrict__ Whh,
        const float* __restrict__ bih, const float* __restrict__ bhh,
        float* __restrict__ outp) {
    constexpr int KIN  = GRP ? 512 : 256;            // non-recurrent K
    constexpr int KTOT = KIN + 512;
    constexpr int ROWB = KTOT * 2;                   // W smem row bytes
    constexpr int W_OFF = 1024;
    constexpr int R_OFF = W_OFF + 32 * ROWB;         // own-h staging (64 x 512h, arb 1024)
    constexpr int P_OFF = R_OFF + 65536;             // NR prefetch buffer
    constexpr int P_ARB = KIN * 2;                   // P row bytes
    // stash: grp1 aliases P (time-disjoint); grp0 has a dedicated region
    const int ST_OFF = GRP ? P_OFF : (P_OFF + 32768);

    __half* hbuf  = GRP ? g_h1 : g_h0;
    unsigned* own = GRP ? &g_c1 : &g_c0;

    uint32_t smb = (uint32_t)__cvta_generic_to_shared(dsm);
    float* stash = (float*)(dsm + ST_OFF);           // 4 x [64 rows x 34 floats]
    float* bsm   = (float*)(dsm + 64);
    int tid = threadIdx.x, lane = tid & 31, w = tid >> 5;
    int m0 = (w & 3) * 16, kq = w >> 2;

    // ---- load & convert W slice: 32 rows ([Wih|Whh] along k), swizzled fp16, resident ----
    for (int idx = tid; idx < 32 * (KTOT / 4); idx += 512) {
        int n  = idx / (KTOT / 4);
        int kk = (idx % (KTOT / 4)) * 4;
        int gr = (n >> 3) * HH + lx * 8 + (n & 7);
        float4 v = (kk < KIN) ? *(const float4*)(Wih + (size_t)gr * KIN + kk)
                              : *(const float4*)(Whh + (size_t)gr * HH + (kk - KIN));
        __half2 p0 = __floats2half2_rn(v.x, v.y);
        __half2 p1 = __floats2half2_rn(v.z, v.w);
        char* dst = dsm + W_OFF + n * ROWB + (((kk >> 3) ^ (n & 7)) << 4) + (kk & 7) * 2;
        *(__half2*)dst       = p0;
        *(__half2*)(dst + 4) = p1;
    }
    if (tid < 32) {
        int gr = (tid >> 3) * HH + lx * 8 + (tid & 7);
        bsm[tid] = bih[gr] + bhh[gr];
    }
    __syncthreads();

    // ---- prologue: establish lag + prefetch P for step 1 ----
    if (GRP == 1) {
        if (tid == 0) { while (ld_acq(&g_c0) < 128u) {} }   // lag 2 behind layer 0
        __syncthreads();
        stage<64>(smb + P_OFF, P_ARB, g_h0 + (size_t)BB * HH, 512);
    } else {
        stage<32>(smb + P_OFF, P_ARB, g_xh, 256);
    }
    cp_commit();

    float cst = 0.f;                                  // c-state for (b=tid>>3, u=tid&7)

    for (int t = 1; t <= TSTEPS; t++) {
        // ===== NR gemm from prefetched P (runs in peers' release-spread shadow) =====
        cp_wait<0>(); __syncthreads();
        float acc[16];
#pragma unroll
        for (int i = 0; i < 16; i++) acc[i] = 0.f;
        if (GRP == 0)
            gemm4<2>(acc, smb + P_OFF, P_ARB, smb + W_OFF, ROWB, kq * 8,  kq * 8);
        else
            gemm4<4>(acc, smb + P_OFF, P_ARB, smb + W_OFF, ROWB, kq * 16, kq * 16);

        // ===== critical path: own recurrence =====
        if (tid == 0) { while (ld_acq(own) < 64u * (t - 1)) {} }
        __syncthreads();
        stage<64>(smb + R_OFF, 1024, hbuf + (size_t)(t - 1) * BB * HH, 512);
        cp_commit(); cp_wait<0>(); __syncthreads();
        gemm4<4>(acc, smb + R_OFF, 1024, smb + W_OFF, ROWB,
                 kq * 16, (GRP ? 64 : 32) + kq * 16);

        // ---- stash partials (4 k-regions, stride 34; grp1 aliases P — safe: all
        //      P reads completed before the poll-sync above) ----
        {
            float* sp = stash + kq * 2176;
            int r0 = m0 + (lane >> 2), cb = 2 * (lane & 3);
#pragma unroll
            for (int nt = 0; nt < 4; nt++) {
                *(float2*)(sp + r0 * 34 + nt * 8 + cb)       =
                    make_float2(acc[nt * 4],     acc[nt * 4 + 1]);
                *(float2*)(sp + (r0 + 8) * 34 + nt * 8 + cb) =
                    make_float2(acc[nt * 4 + 2], acc[nt * 4 + 3]);
            }
        }
        __syncthreads();

        // ---- pointwise LSTM: thread owns (b = tid>>3, u = tid&7) ----
        {
            int b = tid >> 3, u = tid & 7;
            float zi = bsm[u], zf = bsm[8 + u], zg = bsm[16 + u], zo = bsm[24 + u];
#pragma unroll
            for (int q = 0; q < 4; q++) {
                const float* p = stash + q * 2176 + b * 34 + u;
                zi += p[0]; zf += p[8]; zg += p[16]; zo += p[24];
            }
            float iv = 1.f / (1.f + __expf(-zi));
            float fv = 1.f / (1.f + __expf(-zf));
            float gv = tanhf(zg);
            float ov = 1.f / (1.f + __expf(-zo));
            cst = fv * cst + iv * gv;
            float hvf = ov * tanhf(cst);
            hbuf[(size_t)t * BB * HH + b * HH + lx * 8 + u] = __float2half(hvf);
            if (GRP == 1)
                outp[((size_t)b * TSTEPS + (t - 1)) * HH + lx * 8 + u] = hvf;
        }
        __syncthreads();
        if (tid == 0) red_rel(own);               // release: h[t] published

        // ===== prefetch P for step t+1 (lag keeps the grp1 poll instant) =====
        if (t < TSTEPS) {
            if (GRP == 1) {
                if (tid == 0) { while (ld_acq(&g_c0) < 64u * (t + 1)) {} }
                __syncthreads();
                stage<64>(smb + P_OFF, P_ARB, g_h0 + (size_t)(t + 1) * BB * HH, 512);
            } else {
                stage<32>(smb + P_OFF, P_ARB, g_xh + (size_t)t * BB * 256, 256);
            }
            cp_commit();
        }
    }
}

__global__ void __launch_bounds__(512, 1) lstm_fused(
        const float* __restrict__ Wih0, const float* __restrict__ Whh0,
        const float* __restrict__ bih0, const float* __restrict__ bhh0,
        const float* __restrict__ Wih1, const float* __restrict__ Whh1,
        const float* __restrict__ bih1, const float* __restrict__ bhh1,
        float* __restrict__ outp) {
    extern __shared__ char dsm[];
    int bx = blockIdx.x;
    if (bx < 64) run_group<0>(dsm, bx,      Wih0, Whh0, bih0, bhh0, nullptr);
    else         run_group<1>(dsm, bx - 64, Wih1, Whh1, bih1, bhh1, outp);
}

#define SMEM_SZ 197632

// ---------------- host launcher ----------------
extern "C" void kernel_launch(void* const* d_in, const int* in_sizes, int n_in,
                              void* d_out, int out_size) {
    const float* x    = (const float*)d_in[0];
    const float* Wih0 = (const float*)d_in[1];
    const float* Whh0 = (const float*)d_in[2];
    const float* bih0 = (const float*)d_in[3];
    const float* bhh0 = (const float*)d_in[4];
    const float* Wih1 = (const float*)d_in[5];
    const float* Whh1 = (const float*)d_in[6];
    const float* bih1 = (const float*)d_in[7];
    const float* bhh1 = (const float*)d_in[8];
    float* out = (float*)d_out;

    cudaFuncSetAttribute(lstm_fused, cudaFuncAttributeMaxDynamicSharedMemorySize, SMEM_SZ);

    init_k<<<16384, 256>>>(x);
    lstm_fused<<<128, 512, SMEM_SZ>>>(Wih0, Whh0, bih0, bhh0,
                                      Wih1, Whh1, bih1, bhh1, out);
}

// round 12
// speedup vs baseline: 1.2790x; 1.2790x over previous
#include <cuda_runtime.h>
#include <cuda_fp16.h>
#include <cstdint>

#define BB 64
#define TSTEPS 512
#define HH 512

// ---------------- static device scratch ----------------
__device__ __align__(16) __half g_xh[TSTEPS * BB * 256];        // x fp16, [T][B][256]
__device__ __align__(16) __half g_h0[(TSTEPS + 1) * BB * HH];   // layer0 h seq, slot0 = 0
__device__ __align__(16) __half g_h1[(TSTEPS + 1) * BB * HH];   // layer1 h seq, slot0 = 0
// per-CTA publish flags: slot i at stride 32 words (128B) holds last published step
__device__ unsigned g_f0[64 * 32];
__device__ unsigned g_f1[64 * 32];

// ---------------- PTX helpers ----------------
__device__ __forceinline__ void cp16(uint32_t dst, const void* src) {
    asm volatile("cp.async.cg.shared.global [%0], [%1], 16;\n" :: "r"(dst), "l"(src));
}
__device__ __forceinline__ void cp_commit() { asm volatile("cp.async.commit_group;\n"); }
template<int N> __device__ __forceinline__ void cp_wait() {
    asm volatile("cp.async.wait_group %0;\n" :: "n"(N));
}
__device__ __forceinline__ void ldsm4(uint32_t& r0, uint32_t& r1, uint32_t& r2, uint32_t& r3,
                                      uint32_t a) {
    asm volatile("ldmatrix.sync.aligned.m8n8.x4.shared.b16 {%0,%1,%2,%3}, [%4];\n"
                 : "=r"(r0), "=r"(r1), "=r"(r2), "=r"(r3) : "r"(a));
}
__device__ __forceinline__ void mma16816(float* c,
                                         uint32_t a0, uint32_t a1, uint32_t a2, uint32_t a3,
                                         uint32_t b0, uint32_t b1) {
    asm volatile("mma.sync.aligned.m16n8k16.row.col.f32.f16.f16.f32 "
                 "{%0,%1,%2,%3}, {%4,%5,%6,%7}, {%8,%9}, {%0,%1,%2,%3};\n"
                 : "+f"(c[0]), "+f"(c[1]), "+f"(c[2]), "+f"(c[3])
                 : "r"(a0), "r"(a1), "r"(a2), "r"(a3), "r"(b0), "r"(b1));
}
__device__ __forceinline__ unsigned ld_acq(const unsigned* p) {
    unsigned v;
    asm volatile("ld.acquire.gpu.global.u32 %0, [%1];" : "=r"(v) : "l"(p) : "memory");
    return v;
}
__device__ __forceinline__ void st_rel(unsigned* p, unsigned v) {
    asm volatile("st.release.gpu.global.u32 [%0], %1;" :: "l"(p), "r"(v) : "memory");
}
// warp-0 collective: wait until all 64 per-CTA slots >= v
__device__ __forceinline__ void poll_all(const unsigned* base, unsigned v, int lane) {
    const unsigned* p0 = base + lane * 32;
    const unsigned* p1 = base + (lane + 32) * 32;
    for (;;) {
        unsigned a = ld_acq(p0), b = ld_acq(p1);
        if (__all_sync(0xFFFFFFFFu, (a >= v) && (b >= v))) break;
    }
}

// ---------------- A staging: 64 rows x UNITS 16B-units, swizzled (512 thr) ----------------
template<int UNITS>
__device__ __forceinline__ void stage(uint32_t dst, int arb, const __half* src,
                                      int sstride, int kcoff) {
    int tid = threadIdx.x;
#pragma unroll
    for (int i = 0; i < (64 * UNITS) / 512; i++) {
        int idx = tid + i * 512;
        int r = idx / UNITS, kc = idx % UNITS;
        cp16(dst + r * arb + (((kc + kcoff) ^ (r & 7)) << 4), src + r * sstride + kc * 8);
    }
}

// ---------------- GEMM: warp (kq=w>>2, m=w&3) computes 16 rows x 32 cols, K slice ----------------
template<int NP>   // NP iterations of 4 units (64 halves) each
__device__ __forceinline__ void gemm4(float* acc, uint32_t asmb, int arb,
                                      uint32_t wsmb, int rowb, int au0, int wu0) {
    int tid = threadIdx.x, lane = tid & 31, w = tid >> 5;
    int m0 = (w & 3) * 16;
    int rA = m0 + (lane & 15);
    uint32_t abase = asmb + rA * arb;
    int asw = rA & 7, akc = lane >> 4;
    int bm = lane >> 3, bsw = lane & 7;
    uint32_t bb0 = wsmb + (lane & 7) * rowb;
#pragma unroll
    for (int p = 0; p < NP; p++) {
        int au = au0 + 4 * p, wu = wu0 + 4 * p;
        uint32_t a0, a1, a2, a3, a4, a5, a6, a7;
        ldsm4(a0, a1, a2, a3, abase + (((au + akc) ^ asw) << 4));
        ldsm4(a4, a5, a6, a7, abase + (((au + 2 + akc) ^ asw) << 4));
#pragma unroll
        for (int nt = 0; nt < 4; nt++) {
            uint32_t b0, b1, b2, b3;
            ldsm4(b0, b1, b2, b3, bb0 + nt * 8 * rowb + (((wu + bm) ^ bsw) << 4));
            mma16816(acc + nt * 4, a0, a1, a2, a3, b0, b1);
            mma16816(acc + nt * 4, a4, a5, a6, a7, b2, b3);
        }
    }
}

// ---------------- init kernel: x convert + h slot0 zero + flags ----------------
__global__ void init_k(const float* __restrict__ x) {
    int i = blockIdx.x * 256 + threadIdx.x;
    int f2 = i & 127;
    int t  = (i >> 7) & 511;
    int b  = i >> 16;
    float2 v = *(const float2*)(x + ((b * 512 + t) * 256 + f2 * 2));
    *((__half2*)(g_xh + (t * 64 + b) * 256 + f2 * 2)) = __floats2half2_rn(v.x, v.y);
    if (i < 16384) {
        __half2 z = __floats2half2_rn(0.f, 0.f);
        ((__half2*)g_h0)[i] = z;
        ((__half2*)g_h1)[i] = z;
    }
    if (i < 64 * 32) { g_f0[i] = 0; g_f1[i] = 0; }
}

// ---------------- fused two-layer pipelined persistent kernel ----------------
// CTAs [0,64): layer 0.  CTAs [64,128): layer 1, one step behind.
// 512 threads = 16 warps = 4(m) x 4(k-quarter); each warp covers all 32 gate cols.
template<int GRP>
__device__ __forceinline__ void run_group(char* dsm, int lx,
        const float* __restrict__ Wih, const float* __restrict__ Whh,
        const float* __restrict__ bih, const float* __restrict__ bhh,
        float* __restrict__ outp) {
    constexpr int KIN  = GRP ? 512 : 256;
    constexpr int KTOT = KIN + 512;
    constexpr int ROWB = KTOT * 2;                    // W smem row bytes
    constexpr int AOFF = GRP ? 65536 : 49152;         // h staging region (A)
    constexpr int ARB  = GRP ? 2048 : 1024;           // A row bytes
    constexpr int XOFF = 114688;                      // group0 x staging region
    constexpr int BOFF = GRP ? 196608 : 147456;       // bias
    // stash (4 x 64 rows x 40 floats) aliases the A region after gemm completes
    uint32_t smb = (uint32_t)__cvta_generic_to_shared(dsm);
    float* stash = (float*)(dsm + AOFF);
    float* bsm   = (float*)(dsm + BOFF);

    __half* hbuf        = GRP ? g_h1 : g_h0;
    unsigned* own_flags = GRP ? g_f1 : g_f0;

    int tid = threadIdx.x, lane = tid & 31, w = tid >> 5;
    int m0 = (w & 3) * 16, kq = w >> 2;

    // ---- load & convert W slice: 32 rows ([Wih|Whh] along k), swizzled fp16, resident ----
    for (int idx = tid; idx < 32 * (KTOT / 4); idx += 512) {
        int n  = idx / (KTOT / 4);
        int kk = (idx % (KTOT / 4)) * 4;
        int gr = (n >> 3) * HH + lx * 8 + (n & 7);
        float4 v = (kk < KIN) ? *(const float4*)(Wih + (size_t)gr * KIN + kk)
                              : *(const float4*)(Whh + (size_t)gr * HH + (kk - KIN));
        __half2 p0 = __floats2half2_rn(v.x, v.y);
        __half2 p1 = __floats2half2_rn(v.z, v.w);
        char* dst = dsm + n * ROWB + (((kk >> 3) ^ (n & 7)) << 4) + (kk & 7) * 2;
        *(__half2*)dst       = p0;
        *(__half2*)(dst + 4) = p1;
    }
    if (tid < 32) {
        int gr = (tid >> 3) * HH + lx * 8 + (tid & 7);
        bsm[tid] = bih[gr] + bhh[gr];
    }
    __syncthreads();

    float cst = 0.f;                                  // c-state for (b=tid>>3, u=tid&7)
    float acc[16];
#pragma unroll
    for (int i = 0; i < 16; i++) acc[i] = 0.f;

    if (GRP == 0) {   // prologue: x contribution for step 1
        stage<32>(smb + XOFF, 512, g_xh, 256, 0);
        cp_commit(); cp_wait<0>(); __syncthreads();
        gemm4<2>(acc, smb + XOFF, 512, smb, ROWB, kq * 8, kq * 8);
    }

    for (int t = 1; t <= TSTEPS; t++) {
        if (GRP == 0) {
            if (w == 0) poll_all(g_f0, t - 1, lane);
            __syncthreads();
            stage<64>(smb + AOFF, ARB, g_h0 + (size_t)(t - 1) * BB * HH, 512, 0);
            cp_commit(); cp_wait<0>(); __syncthreads();
            gemm4<4>(acc, smb + AOFF, ARB, smb, ROWB, kq * 16, 32 + kq * 16);
        } else {
            // h0[t] input part: group0 runs ahead, so this poll is usually instant
            if (w == 0) poll_all(g_f0, t, lane);
            __syncthreads();
            stage<64>(smb + AOFF, ARB, g_h0 + (size_t)t * BB * HH, 512, 0);
            cp_commit();
            if (w == 0) poll_all(g_f1, t - 1, lane);
            __syncthreads();
            stage<64>(smb + AOFF, ARB, g_h1 + (size_t)(t - 1) * BB * HH, 512, 64);
            cp_commit();
            cp_wait<1>(); __syncthreads();
            gemm4<4>(acc, smb + AOFF, ARB, smb, ROWB, kq * 16, kq * 16);          // h0
            cp_wait<0>(); __syncthreads();
            gemm4<4>(acc, smb + AOFF, ARB, smb, ROWB, 64 + kq * 16, 64 + kq * 16); // h1
        }

        // ---- all A reads done -> safe to alias stash into A region ----
        __syncthreads();
        {
            float* sp = stash + kq * 2560;
            int r0 = m0 + (lane >> 2), cb = 2 * (lane & 3);
#pragma unroll
            for (int nt = 0; nt < 4; nt++) {
                *(float2*)(sp + r0 * 40 + nt * 8 + cb)       =
                    make_float2(acc[nt * 4],     acc[nt * 4 + 1]);
                *(float2*)(sp + (r0 + 8) * 40 + nt * 8 + cb) =
                    make_float2(acc[nt * 4 + 2], acc[nt * 4 + 3]);
            }
        }
        __syncthreads();

        // ---- pointwise LSTM: thread owns (b = tid>>3, u = tid&7) ----
        {
            int b = tid >> 3, u = tid & 7;
            float zi = bsm[u], zf = bsm[8 + u], zg = bsm[16 + u], zo = bsm[24 + u];
#pragma unroll
            for (int q = 0; q < 4; q++) {
                const float* p = stash + q * 2560 + b * 40 + u;
                zi += p[0]; zf += p[8]; zg += p[16]; zo += p[24];
            }
            float iv = 1.f / (1.f + __expf(-zi));
            float fv = 1.f / (1.f + __expf(-zf));
            float gv = tanhf(zg);
            float ov = 1.f / (1.f + __expf(-zo));
            cst = fv * cst + iv * gv;
            float hvf = ov * tanhf(cst);
            hbuf[(size_t)t * BB * HH + b * HH + lx * 8 + u] = __float2half(hvf);
            if (GRP == 1)
                outp[((size_t)b * TSTEPS + (t - 1)) * HH + lx * 8 + u] = hvf;
        }
        __syncthreads();
        if (tid == 0) st_rel(&own_flags[lx * 32], t);   // publish h[t]: own slot, no contention

#pragma unroll
        for (int i = 0; i < 16; i++) acc[i] = 0.f;

        if (GRP == 0 && t < TSTEPS) {   // x(t+1) GEMM in the publish shadow
            stage<32>(smb + XOFF, 512, g_xh + (size_t)t * BB * 256, 256, 0);
            cp_commit(); cp_wait<0>(); __syncthreads();
            gemm4<2>(acc, smb + XOFF, 512, smb, ROWB, kq * 8, kq * 8);
        }
    }
}

__global__ void __launch_bounds__(512, 1) lstm_fused(
        const float* __restrict__ Wih0, const float* __restrict__ Whh0,
        const float* __restrict__ bih0, const float* __restrict__ bhh0,
        const float* __restrict__ Wih1, const float* __restrict__ Whh1,
        const float* __restrict__ bih1, const float* __restrict__ bhh1,
        float* __restrict__ outp) {
    extern __shared__ char dsm[];
    int bx = blockIdx.x;
    if (bx < 64) run_group<0>(dsm, bx,      Wih0, Whh0, bih0, bhh0, nullptr);
    else         run_group<1>(dsm, bx - 64, Wih1, Whh1, bih1, bhh1, outp);
}

// ---------------- host launcher ----------------
extern "C" void kernel_launch(void* const* d_in, const int* in_sizes, int n_in,
                              void* d_out, int out_size) {
    const float* x    = (const float*)d_in[0];
    const float* Wih0 = (const float*)d_in[1];
    const float* Whh0 = (const float*)d_in[2];
    const float* bih0 = (const float*)d_in[3];
    const float* bhh0 = (const float*)d_in[4];
    const float* Wih1 = (const float*)d_in[5];
    const float* Whh1 = (const float*)d_in[6];
    const float* bih1 = (const float*)d_in[7];
    const float* bhh1 = (const float*)d_in[8];
    float* out = (float*)d_out;

    cudaFuncSetAttribute(lstm_fused, cudaFuncAttributeMaxDynamicSharedMemorySize, 197120);

    init_k<<<16384, 256>>>(x);
    lstm_fused<<<128, 512, 197120>>>(Wih0, Whh0, bih0, bhh0,
                                     Wih1, Whh1, bih1, bhh1, out);
}

// round 13
// speedup vs baseline: 1.3567x; 1.0607x over previous
#include <cuda_runtime.h>
#include <cuda_fp16.h>
#include <cstdint>

#define BB 64
#define TSTEPS 512
#define HH 512

// ---------------- static device scratch ----------------
__device__ __align__(16) __half g_xh[TSTEPS * BB * 256];        // x fp16, [T][B][256]
__device__ __align__(16) __half g_h0[(TSTEPS + 1) * BB * HH];   // layer0 h seq, slot0 = 0
__device__ __align__(16) __half g_h1[(TSTEPS + 1) * BB * HH];   // layer1 h seq, slot0 = 0
__device__ unsigned g_c0;                                       // monotonic arrival counters
__device__ unsigned g_c1;

// ---------------- PTX helpers ----------------
__device__ __forceinline__ void cp16(uint32_t dst, const void* src) {
    asm volatile("cp.async.cg.shared.global [%0], [%1], 16;\n" :: "r"(dst), "l"(src));
}
__device__ __forceinline__ void cp_commit() { asm volatile("cp.async.commit_group;\n"); }
template<int N> __device__ __forceinline__ void cp_wait() {
    asm volatile("cp.async.wait_group %0;\n" :: "n"(N));
}
__device__ __forceinline__ void ldsm4(uint32_t& r0, uint32_t& r1, uint32_t& r2, uint32_t& r3,
                                      uint32_t a) {
    asm volatile("ldmatrix.sync.aligned.m8n8.x4.shared.b16 {%0,%1,%2,%3}, [%4];\n"
                 : "=r"(r0), "=r"(r1), "=r"(r2), "=r"(r3) : "r"(a));
}
// fp16-accumulate HMMA: 2x issue throughput of the fp32-acc form
__device__ __forceinline__ void mma16816h(uint32_t* c,
                                          uint32_t a0, uint32_t a1, uint32_t a2, uint32_t a3,
                                          uint32_t b0, uint32_t b1) {
    asm volatile("mma.sync.aligned.m16n8k16.row.col.f16.f16.f16.f16 "
                 "{%0,%1}, {%2,%3,%4,%5}, {%6,%7}, {%0,%1};\n"
                 : "+r"(c[0]), "+r"(c[1])
                 : "r"(a0), "r"(a1), "r"(a2), "r"(a3), "r"(b0), "r"(b1));
}
__device__ __forceinline__ unsigned ld_acq(const unsigned* p) {
    unsigned v;
    asm volatile("ld.acquire.gpu.global.u32 %0, [%1];" : "=r"(v) : "l"(p) : "memory");
    return v;
}
__device__ __forceinline__ void red_rel(unsigned* p) {
    asm volatile("red.release.gpu.global.add.u32 [%0], 1;" :: "l"(p) : "memory");
}

// ---------------- A staging: 64 rows x UNITS 16B-units, swizzled (512 thr) ----------------
template<int UNITS>
__device__ __forceinline__ void stage(uint32_t dst, int arb, const __half* src,
                                      int sstride, int kcoff) {
    int tid = threadIdx.x;
#pragma unroll
    for (int i = 0; i < (64 * UNITS) / 512; i++) {
        int idx = tid + i * 512;
        int r = idx / UNITS, kc = idx % UNITS;
        cp16(dst + r * arb + (((kc + kcoff) ^ (r & 7)) << 4), src + r * sstride + kc * 8);
    }
}

// ---------------- GEMM: warp (kq=w>>2, m=w&3), 16 rows x 32 cols, fp16 acc ----------------
template<int NP>   // NP iterations of 4 units (64 halves) each
__device__ __forceinline__ void gemm4(uint32_t* hacc, uint32_t asmb, int arb,
                                      uint32_t wsmb, int rowb, int au0, int wu0) {
    int tid = threadIdx.x, lane = tid & 31, w = tid >> 5;
    int m0 = (w & 3) * 16;
    int rA = m0 + (lane & 15);
    uint32_t abase = asmb + rA * arb;
    int asw = rA & 7, akc = lane >> 4;
    int bm = lane >> 3, bsw = lane & 7;
    uint32_t bb0 = wsmb + (lane & 7) * rowb;
#pragma unroll
    for (int p = 0; p < NP; p++) {
        int au = au0 + 4 * p, wu = wu0 + 4 * p;
        uint32_t a0, a1, a2, a3, a4, a5, a6, a7;
        ldsm4(a0, a1, a2, a3, abase + (((au + akc) ^ asw) << 4));
        ldsm4(a4, a5, a6, a7, abase + (((au + 2 + akc) ^ asw) << 4));
#pragma unroll
        for (int nt = 0; nt < 4; nt++) {
            uint32_t b0, b1, b2, b3;
            ldsm4(b0, b1, b2, b3, bb0 + nt * 8 * rowb + (((wu + bm) ^ bsw) << 4));
            mma16816h(hacc + nt * 2, a0, a1, a2, a3, b0, b1);
            mma16816h(hacc + nt * 2, a4, a5, a6, a7, b2, b3);
        }
    }
}

// ---------------- init kernel: x convert + h slot0 zero + counters ----------------
__global__ void init_k(const float* __restrict__ x) {
    int i = blockIdx.x * 256 + threadIdx.x;
    int f2 = i & 127;
    int t  = (i >> 7) & 511;
    int b  = i >> 16;
    float2 v = *(const float2*)(x + ((b * 512 + t) * 256 + f2 * 2));
    *((__half2*)(g_xh + (t * 64 + b) * 256 + f2 * 2)) = __floats2half2_rn(v.x, v.y);
    if (i < 16384) {
        __half2 z = __floats2half2_rn(0.f, 0.f);
        ((__half2*)g_h0)[i] = z;
        ((__half2*)g_h1)[i] = z;
    }
    if (i == 0) { g_c0 = 0; g_c1 = 0; }
}

// ---------------- fused two-layer pipelined persistent kernel ----------------
// CTAs [0,64): layer 0.  CTAs [64,128): layer 1, one step behind.
// 512 threads = 16 warps = 4(m) x 4(k-quarter); each warp covers all 32 gate cols.
// Accumulation: fp16 within each k-quarter (<=16 roundings), fp32 across quarters.
template<int GRP>
__device__ __forceinline__ void run_group(char* dsm, int lx,
        const float* __restrict__ Wih, const float* __restrict__ Whh,
        const float* __restrict__ bih, const float* __restrict__ bhh,
        float* __restrict__ outp) {
    constexpr int KIN  = GRP ? 512 : 256;
    constexpr int KTOT = KIN + 512;
    constexpr int ROWB = KTOT * 2;                    // W smem row bytes
    constexpr int AOFF = GRP ? 65536 : 49152;         // h staging region (A)
    constexpr int ARB  = GRP ? 2048 : 1024;           // A row bytes
    constexpr int XOFF = 114688;                      // group0 x staging region
    constexpr int BOFF = GRP ? 196608 : 147456;       // bias
    // stash (4 x 64 rows x 40 floats) aliases the A region after gemm completes
    uint32_t smb = (uint32_t)__cvta_generic_to_shared(dsm);
    float* stash = (float*)(dsm + AOFF);
    float* bsm   = (float*)(dsm + BOFF);

    __half* hbuf  = GRP ? g_h1 : g_h0;
    unsigned* own = GRP ? &g_c1 : &g_c0;

    int tid = threadIdx.x, lane = tid & 31, w = tid >> 5;
    int m0 = (w & 3) * 16, kq = w >> 2;

    // ---- load & convert W slice: 32 rows ([Wih|Whh] along k), swizzled fp16, resident ----
    for (int idx = tid; idx < 32 * (KTOT / 4); idx += 512) {
        int n  = idx / (KTOT / 4);
        int kk = (idx % (KTOT / 4)) * 4;
        int gr = (n >> 3) * HH + lx * 8 + (n & 7);
        float4 v = (kk < KIN) ? *(const float4*)(Wih + (size_t)gr * KIN + kk)
                              : *(const float4*)(Whh + (size_t)gr * HH + (kk - KIN));
        __half2 p0 = __floats2half2_rn(v.x, v.y);
        __half2 p1 = __floats2half2_rn(v.z, v.w);
        char* dst = dsm + n * ROWB + (((kk >> 3) ^ (n & 7)) << 4) + (kk & 7) * 2;
        *(__half2*)dst       = p0;
        *(__half2*)(dst + 4) = p1;
    }
    if (tid < 32) {
        int gr = (tid >> 3) * HH + lx * 8 + (tid & 7);
        bsm[tid] = bih[gr] + bhh[gr];
    }
    __syncthreads();

    float cst = 0.f;                                  // c-state for (b=tid>>3, u=tid&7)
    uint32_t hacc[8];
#pragma unroll
    for (int i = 0; i < 8; i++) hacc[i] = 0u;

    if (GRP == 0) {   // prologue: x contribution for step 1
        stage<32>(smb + XOFF, 512, g_xh, 256, 0);
        cp_commit(); cp_wait<0>(); __syncthreads();
        gemm4<2>(hacc, smb + XOFF, 512, smb, ROWB, kq * 8, kq * 8);
    }

    for (int t = 1; t <= TSTEPS; t++) {
        if (GRP == 0) {
            if (tid == 0) { while (ld_acq(&g_c0) < 64u * (t - 1)) {} }
            __syncthreads();
            stage<64>(smb + AOFF, ARB, g_h0 + (size_t)(t - 1) * BB * HH, 512, 0);
            cp_commit(); cp_wait<0>(); __syncthreads();
            gemm4<4>(hacc, smb + AOFF, ARB, smb, ROWB, kq * 16, 32 + kq * 16);
        } else {
            // h0[t] input part: group0 runs ahead, so this poll is usually instant
            if (tid == 0) { while (ld_acq(&g_c0) < 64u * t) {} }
            __syncthreads();
            stage<64>(smb + AOFF, ARB, g_h0 + (size_t)t * BB * HH, 512, 0);
            cp_commit();
            if (tid == 0) { while (ld_acq(&g_c1) < 64u * (t - 1)) {} }
            __syncthreads();
            stage<64>(smb + AOFF, ARB, g_h1 + (size_t)(t - 1) * BB * HH, 512, 64);
            cp_commit();
            cp_wait<1>(); __syncthreads();
            gemm4<4>(hacc, smb + AOFF, ARB, smb, ROWB, kq * 16, kq * 16);          // h0
            cp_wait<0>(); __syncthreads();
            gemm4<4>(hacc, smb + AOFF, ARB, smb, ROWB, 64 + kq * 16, 64 + kq * 16); // h1
        }

        // ---- all A reads done -> safe to alias stash into A region ----
        __syncthreads();
        {
            float* sp = stash + kq * 2560;
            int r0 = m0 + (lane >> 2), cb = 2 * (lane & 3);
#pragma unroll
            for (int nt = 0; nt < 4; nt++) {
                float2 f01 = __half22float2(*(__half2*)&hacc[nt * 2]);
                float2 f23 = __half22float2(*(__half2*)&hacc[nt * 2 + 1]);
                *(float2*)(sp + r0 * 40 + nt * 8 + cb)       = f01;
                *(float2*)(sp + (r0 + 8) * 40 + nt * 8 + cb) = f23;
            }
        }
        __syncthreads();

        // ---- pointwise LSTM: thread owns (b = tid>>3, u = tid&7); fp32 reduce ----
        {
            int b = tid >> 3, u = tid & 7;
            float zi = bsm[u], zf = bsm[8 + u], zg = bsm[16 + u], zo = bsm[24 + u];
#pragma unroll
            for (int q = 0; q < 4; q++) {
                const float* p = stash + q * 2560 + b * 40 + u;
                zi += p[0]; zf += p[8]; zg += p[16]; zo += p[24];
            }
            float iv = 1.f / (1.f + __expf(-zi));
            float fv = 1.f / (1.f + __expf(-zf));
            float gv = tanhf(zg);
            float ov = 1.f / (1.f + __expf(-zo));
            cst = fv * cst + iv * gv;
            float hvf = ov * tanhf(cst);
            hbuf[(size_t)t * BB * HH + b * HH + lx * 8 + u] = __float2half(hvf);
            if (GRP == 1)
                outp[((size_t)b * TSTEPS + (t - 1)) * HH + lx * 8 + u] = hvf;
        }
        __syncthreads();
        if (tid == 0) red_rel(own);   // release: h[t] published

#pragma unroll
        for (int i = 0; i < 8; i++) hacc[i] = 0u;

        if (GRP == 0 && t < TSTEPS) {   // x(t+1) GEMM in the publish shadow
            stage<32>(smb + XOFF, 512, g_xh + (size_t)t * BB * 256, 256, 0);
            cp_commit(); cp_wait<0>(); __syncthreads();
            gemm4<2>(hacc, smb + XOFF, 512, smb, ROWB, kq * 8, kq * 8);
        }
    }
}

__global__ void __launch_bounds__(512, 1) lstm_fused(
        const float* __restrict__ Wih0, const float* __restrict__ Whh0,
        const float* __restrict__ bih0, const float* __restrict__ bhh0,
        const float* __restrict__ Wih1, const float* __restrict__ Whh1,
        const float* __restrict__ bih1, const float* __restrict__ bhh1,
        float* __restrict__ outp) {
    extern __shared__ char dsm[];
    int bx = blockIdx.x;
    if (bx < 64) run_group<0>(dsm, bx,      Wih0, Whh0, bih0, bhh0, nullptr);
    else         run_group<1>(dsm, bx - 64, Wih1, Whh1, bih1, bhh1, outp);
}

// ---------------- host launcher ----------------
extern "C" void kernel_launch(void* const* d_in, const int* in_sizes, int n_in,
                              void* d_out, int out_size) {
    const float* x    = (const float*)d_in[0];
    const float* Wih0 = (const float*)d_in[1];
    const float* Whh0 = (const float*)d_in[2];
    const float* bih0 = (const float*)d_in[3];
    const float* bhh0 = (const float*)d_in[4];
    const float* Wih1 = (const float*)d_in[5];
    const float* Whh1 = (const float*)d_in[6];
    const float* bih1 = (const float*)d_in[7];
    const float* bhh1 = (const float*)d_in[8];
    float* out = (float*)d_out;

    cudaFuncSetAttribute(lstm_fused, cudaFuncAttributeMaxDynamicSharedMemorySize, 197120);

    init_k<<<16384, 256>>>(x);
    lstm_fused<<<128, 512, 197120>>>(Wih0, Whh0, bih0, bhh0,
                                     Wih1, Whh1, bih1, bhh1, out);
}

// round 14
// speedup vs baseline: 1.3706x; 1.0102x over previous
#include <cuda_runtime.h>
#include <cuda_fp16.h>
#include <cstdint>

#define BB 64
#define TSTEPS 512
#define HH 512

// ---------------- static device scratch ----------------
__device__ __align__(16) __half g_xh[TSTEPS * BB * 256];        // x fp16, [T][B][256]
__device__ __align__(16) __half g_h0[(TSTEPS + 1) * BB * HH];   // layer0 h seq, slot0 = 0
__device__ __align__(16) __half g_h1[(TSTEPS + 1) * BB * HH];   // layer1 h seq, slot0 = 0
__device__ unsigned g_c0;                                       // monotonic arrival counters
__device__ unsigned g_c1;

// ---------------- PTX helpers ----------------
__device__ __forceinline__ void cp16(uint32_t dst, const void* src) {
    asm volatile("cp.async.cg.shared.global [%0], [%1], 16;\n" :: "r"(dst), "l"(src));
}
__device__ __forceinline__ void cp_commit() { asm volatile("cp.async.commit_group;\n"); }
template<int N> __device__ __forceinline__ void cp_wait() {
    asm volatile("cp.async.wait_group %0;\n" :: "n"(N));
}
__device__ __forceinline__ void ldsm4(uint32_t& r0, uint32_t& r1, uint32_t& r2, uint32_t& r3,
                                      uint32_t a) {
    asm volatile("ldmatrix.sync.aligned.m8n8.x4.shared.b16 {%0,%1,%2,%3}, [%4];\n"
                 : "=r"(r0), "=r"(r1), "=r"(r2), "=r"(r3) : "r"(a));
}
__device__ __forceinline__ void mma16816(float* c,
                                         uint32_t a0, uint32_t a1, uint32_t a2, uint32_t a3,
                                         uint32_t b0, uint32_t b1) {
    asm volatile("mma.sync.aligned.m16n8k16.row.col.f32.f16.f16.f32 "
                 "{%0,%1,%2,%3}, {%4,%5,%6,%7}, {%8,%9}, {%0,%1,%2,%3};\n"
                 : "+f"(c[0]), "+f"(c[1]), "+f"(c[2]), "+f"(c[3])
                 : "r"(a0), "r"(a1), "r"(a2), "r"(a3), "r"(b0), "r"(b1));
}
__device__ __forceinline__ unsigned ld_acq(const unsigned* p) {
    unsigned v;
    asm volatile("ld.acquire.gpu.global.u32 %0, [%1];" : "=r"(v) : "l"(p) : "memory");
    return v;
}
__device__ __forceinline__ void red_rel(unsigned* p) {
    asm volatile("red.release.gpu.global.add.u32 [%0], 1;" :: "l"(p) : "memory");
}
// warp-collective poll: all lanes spin on the same counter (one coalesced request)
__device__ __forceinline__ void wpoll(const unsigned* p, unsigned v) {
    while (ld_acq(p) < v) {}
}

// ---------------- per-warp A staging: warp w stages rows [4w, 4w+4) ----------------
template<int UNITS>
__device__ __forceinline__ void stage_w(uint32_t dst, int arb, const __half* src,
                                        int sstride, int kcoff, int w, int lane) {
#pragma unroll
    for (int i = 0; i < UNITS / 8; i++) {         // 4 rows * UNITS units / 32 lanes
        int idx = lane + i * 32;
        int r = w * 4 + idx / UNITS;
        int kc = idx % UNITS;
        cp16(dst + r * arb + (((kc + kcoff) ^ (r & 7)) << 4), src + r * sstride + kc * 8);
    }
}

// ---------------- GEMM: warp (kq=w>>2, m=w&3) computes 16 rows x 32 cols, K slice ----------------
template<int NP>   // NP iterations of 4 units (64 halves) each
__device__ __forceinline__ void gemm4(float* acc, uint32_t asmb, int arb,
                                      uint32_t wsmb, int rowb, int au0, int wu0) {
    int tid = threadIdx.x, lane = tid & 31, w = tid >> 5;
    int m0 = (w & 3) * 16;
    int rA = m0 + (lane & 15);
    uint32_t abase = asmb + rA * arb;
    int asw = rA & 7, akc = lane >> 4;
    int bm = lane >> 3, bsw = lane & 7;
    uint32_t bb0 = wsmb + (lane & 7) * rowb;
#pragma unroll
    for (int p = 0; p < NP; p++) {
        int au = au0 + 4 * p, wu = wu0 + 4 * p;
        uint32_t a0, a1, a2, a3, a4, a5, a6, a7;
        ldsm4(a0, a1, a2, a3, abase + (((au + akc) ^ asw) << 4));
        ldsm4(a4, a5, a6, a7, abase + (((au + 2 + akc) ^ asw) << 4));
#pragma unroll
        for (int nt = 0; nt < 4; nt++) {
            uint32_t b0, b1, b2, b3;
            ldsm4(b0, b1, b2, b3, bb0 + nt * 8 * rowb + (((wu + bm) ^ bsw) << 4));
            mma16816(acc + nt * 4, a0, a1, a2, a3, b0, b1);
            mma16816(acc + nt * 4, a4, a5, a6, a7, b2, b3);
        }
    }
}

// ---------------- init kernel: x convert + h slot0 zero + counters ----------------
__global__ void init_k(const float* __restrict__ x) {
    int i = blockIdx.x * 256 + threadIdx.x;
    int f2 = i & 127;
    int t  = (i >> 7) & 511;
    int b  = i >> 16;
    float2 v = *(const float2*)(x + ((b * 512 + t) * 256 + f2 * 2));
    *((__half2*)(g_xh + (t * 64 + b) * 256 + f2 * 2)) = __floats2half2_rn(v.x, v.y);
    if (i < 16384) {
        __half2 z = __floats2half2_rn(0.f, 0.f);
        ((__half2*)g_h0)[i] = z;
        ((__half2*)g_h1)[i] = z;
    }
    if (i == 0) { g_c0 = 0; g_c1 = 0; }
}

// ---------------- fused two-layer pipelined persistent kernel ----------------
// CTAs [0,64): layer 0.  CTAs [64,128): layer 1, one step behind.
// 512 threads = 16 warps = 4(m) x 4(k-quarter); each warp covers all 32 gate cols.
// Handoff: per-warp poll + per-warp immediate staging (no block sync on the poll).
template<int GRP>
__device__ __forceinline__ void run_group(char* dsm, int lx,
        const float* __restrict__ Wih, const float* __restrict__ Whh,
        const float* __restrict__ bih, const float* __restrict__ bhh,
        float* __restrict__ outp) {
    constexpr int KIN  = GRP ? 512 : 256;
    constexpr int KTOT = KIN + 512;
    constexpr int ROWB = KTOT * 2;                    // W smem row bytes
    constexpr int AOFF = GRP ? 65536 : 49152;         // h staging region (A)
    constexpr int ARB  = GRP ? 2048 : 1024;           // A row bytes
    constexpr int XOFF = 114688;                      // group0 x staging region
    constexpr int BOFF = GRP ? 196608 : 147456;       // bias
    // stash (4 x 64 rows x 40 floats) aliases the A region after gemm completes
    uint32_t smb = (uint32_t)__cvta_generic_to_shared(dsm);
    float* stash = (float*)(dsm + AOFF);
    float* bsm   = (float*)(dsm + BOFF);

    __half* hbuf  = GRP ? g_h1 : g_h0;
    unsigned* own = GRP ? &g_c1 : &g_c0;

    int tid = threadIdx.x, lane = tid & 31, w = tid >> 5;
    int m0 = (w & 3) * 16, kq = w >> 2;

    // ---- load & convert W slice: 32 rows ([Wih|Whh] along k), swizzled fp16, resident ----
    for (int idx = tid; idx < 32 * (KTOT / 4); idx += 512) {
        int n  = idx / (KTOT / 4);
        int kk = (idx % (KTOT / 4)) * 4;
        int gr = (n >> 3) * HH + lx * 8 + (n & 7);
        float4 v = (kk < KIN) ? *(const float4*)(Wih + (size_t)gr * KIN + kk)
                              : *(const float4*)(Whh + (size_t)gr * HH + (kk - KIN));
        __half2 p0 = __floats2half2_rn(v.x, v.y);
        __half2 p1 = __floats2half2_rn(v.z, v.w);
        char* dst = dsm + n * ROWB + (((kk >> 3) ^ (n & 7)) << 4) + (kk & 7) * 2;
        *(__half2*)dst       = p0;
        *(__half2*)(dst + 4) = p1;
    }
    if (tid < 32) {
        int gr = (tid >> 3) * HH + lx * 8 + (tid & 7);
        bsm[tid] = bih[gr] + bhh[gr];
    }
    __syncthreads();

    float cst = 0.f;                                  // c-state for (b=tid>>3, u=tid&7)
    float acc[16];
#pragma unroll
    for (int i = 0; i < 16; i++) acc[i] = 0.f;

    if (GRP == 0) {   // prologue: x contribution for step 1
        stage_w<32>(smb + XOFF, 512, g_xh, 256, 0, w, lane);
        cp_commit(); cp_wait<0>(); __syncthreads();
        gemm4<2>(acc, smb + XOFF, 512, smb, ROWB, kq * 8, kq * 8);
    }

    for (int t = 1; t <= TSTEPS; t++) {
        if (GRP == 0) {
            // per-warp: poll, then stage own 4 rows immediately
            wpoll(&g_c0, 64u * (t - 1));
            stage_w<64>(smb + AOFF, ARB, g_h0 + (size_t)(t - 1) * BB * HH, 512, 0, w, lane);
            cp_commit();
            cp_wait<0>(); __syncthreads();
            gemm4<4>(acc, smb + AOFF, ARB, smb, ROWB, kq * 16, 32 + kq * 16);
        } else {
            // h0[t] input part: group0 runs ahead, so this poll is usually instant
            wpoll(&g_c0, 64u * t);
            stage_w<64>(smb + AOFF, ARB, g_h0 + (size_t)t * BB * HH, 512, 0, w, lane);
            cp_commit();
            wpoll(&g_c1, 64u * (t - 1));
            stage_w<64>(smb + AOFF, ARB, g_h1 + (size_t)(t - 1) * BB * HH, 512, 64, w, lane);
            cp_commit();
            cp_wait<1>(); __syncthreads();
            gemm4<4>(acc, smb + AOFF, ARB, smb, ROWB, kq * 16, kq * 16);          // h0
            cp_wait<0>(); __syncthreads();
            gemm4<4>(acc, smb + AOFF, ARB, smb, ROWB, 64 + kq * 16, 64 + kq * 16); // h1
        }

        // ---- all A reads done -> safe to alias stash into A region ----
        __syncthreads();
        {
            float* sp = stash + kq * 2560;
            int r0 = m0 + (lane >> 2), cb = 2 * (lane & 3);
#pragma unroll
            for (int nt = 0; nt < 4; nt++) {
                *(float2*)(sp + r0 * 40 + nt * 8 + cb)       =
                    make_float2(acc[nt * 4],     acc[nt * 4 + 1]);
                *(float2*)(sp + (r0 + 8) * 40 + nt * 8 + cb) =
                    make_float2(acc[nt * 4 + 2], acc[nt * 4 + 3]);
            }
        }
        __syncthreads();

        // ---- pointwise LSTM: thread owns (b = tid>>3, u = tid&7) ----
        {
            int b = tid >> 3, u = tid & 7;
            float zi = bsm[u], zf = bsm[8 + u], zg = bsm[16 + u], zo = bsm[24 + u];
#pragma unroll
            for (int q = 0; q < 4; q++) {
                const float* p = stash + q * 2560 + b * 40 + u;
                zi += p[0]; zf += p[8]; zg += p[16]; zo += p[24];
            }
            float iv = 1.f / (1.f + __expf(-zi));
            float fv = 1.f / (1.f + __expf(-zf));
            float gv = tanhf(zg);
            float ov = 1.f / (1.f + __expf(-zo));
            cst = fv * cst + iv * gv;
            float hvf = ov * tanhf(cst);
            hbuf[(size_t)t * BB * HH + b * HH + lx * 8 + u] = __float2half(hvf);
            if (GRP == 1)
                outp[((size_t)b * TSTEPS + (t - 1)) * HH + lx * 8 + u] = hvf;
        }
        __syncthreads();
        if (tid == 0) red_rel(own);   // release: h[t] published

#pragma unroll
        for (int i = 0; i < 16; i++) acc[i] = 0.f;

        if (GRP == 0 && t < TSTEPS) {   // x(t+1) GEMM in the publish shadow
            stage_w<32>(smb + XOFF, 512, g_xh + (size_t)t * BB * 256, 256, 0, w, lane);
            cp_commit(); cp_wait<0>(); __syncthreads();
            gemm4<2>(acc, smb + XOFF, 512, smb, ROWB, kq * 8, kq * 8);
        }
    }
}

__global__ void __launch_bounds__(512, 1) lstm_fused(
        const float* __restrict__ Wih0, const float* __restrict__ Whh0,
        const float* __restrict__ bih0, const float* __restrict__ bhh0,
        const float* __restrict__ Wih1, const float* __restrict__ Whh1,
        const float* __restrict__ bih1, const float* __restrict__ bhh1,
        float* __restrict__ outp) {
    extern __shared__ char dsm[];
    int bx = blockIdx.x;
    if (bx < 64) run_group<0>(dsm, bx,      Wih0, Whh0, bih0, bhh0, nullptr);
    else         run_group<1>(dsm, bx - 64, Wih1, Whh1, bih1, bhh1, outp);
}

// ---------------- host launcher ----------------
extern "C" void kernel_launch(void* const* d_in, const int* in_sizes, int n_in,
                              void* d_out, int out_size) {
    const float* x    = (const float*)d_in[0];
    const float* Wih0 = (const float*)d_in[1];
    const float* Whh0 = (const float*)d_in[2];
    const float* bih0 = (const float*)d_in[3];
    const float* bhh0 = (const float*)d_in[4];
    const float* Wih1 = (const float*)d_in[5];
    const float* Whh1 = (const float*)d_in[6];
    const float* bih1 = (const float*)d_in[7];
    const float* bhh1 = (const float*)d_in[8];
    float* out = (float*)d_out;

    cudaFuncSetAttribute(lstm_fused, cudaFuncAttributeMaxDynamicSharedMemorySize, 197120);

    init_k<<<16384, 256>>>(x);
    lstm_fused<<<128, 512, 197120>>>(Wih0, Whh0, bih0, bhh0,
                                     Wih1, Whh1, bih1, bhh1, out);
}